// round 11
// baseline (speedup 1.0000x reference)
#include <cuda_runtime.h>
#include <cuda_bf16.h>
#include <stdint.h>

#define NPW 16
#define M   64
#define NT  1024           // 32 warps, 8/SMSP
#define NW  (NT / 32)
#define NG  16             // row groups for m^2 phases: 16 groups x 4 rows
#define OBJ 10
#define NPAIRS 2016        // off-diagonal pairs (j<k) for hot loop
#define NPAIRS2 2080       // pairs incl. diagonal (r<=c) for phase 2
#define PPT 2
#define DSTR 68            // dsT row stride (floats)

#define MAGIC 12582912.0f  // 1.5*2^23; bits(MAGIC + n) = 0x4B400000 + n

// Dynamic shared memory layout (bytes); all offsets 16B-aligned
#define OFF_DST   0u          // dsT[c*68 + r], pre-scaled by 16      (17408)
#define OFF_SIM   17408u      // (16384)
#define OFF_AM    33792u      // (16384)
#define OFF_T03   50176u      // float4[19*16]  f0 .xy / f3 .zw       (4864)
#define OFF_T14   55040u      // float4[19*16]  f1 .xy / f4 .zw       (4864)
#define OFF_T6    62336u      // float2[19*16]                        (2432)
#define OFF_T5    64768u      // float2[19*16]                        (2432)
#define OFF_T7    67200u      // float2[19] + pad                     (160)
#define OFF_TAB   67360u      // float2[8*17] (csum, w_next)          (1088)
#define OFF_ATT   68448u
#define OFF_AREA  68704u
#define OFF_BX1   68960u
#define OFF_BY1   69216u
#define OFF_BX2   69472u
#define OFF_BY2   69728u
#define OFF_PART  69984u      // NG*64*4 = 4096
#define OFF_RINV  74080u
#define OFF_WRA   74336u      // 32 floats
#define OFF_WRB   74464u      // 32 floats
#define SMEM_TOTAL 74592u

// Protected magic-add: __fadd_rn is never merged/reassociated, so the -0.5
// bias cannot be refolded into MAGIC by fast-math (the R5/R6 bug).
__device__ __forceinline__ uint32_t magic_bits(float t) {
    return __float_as_uint(__fadd_rn(t, MAGIC));
}

// Fused-table entry for slot = n+1 (n = -1..17):
//   val(x) = T0 + (16x)*T1 on segment n, T0 = csum[n] - n*w_next, T1 = w_next.
//   slot 0 (n=-1) encodes the reference's x<0 branch.
__device__ __forceinline__ float2 fused_entry(const float2* __restrict__ t, int slot) {
    if (slot == 0) {
        float cs0 = t[0].x, w1 = t[0].y;
        return make_float2(cs0 + w1, w1);
    }
    int n = slot - 1; if (n > 16) n = 16;
    float2 v = t[n];
    return make_float2(fmaf(-(float)n, v.y, v.x), v.y);
}

__global__ __launch_bounds__(NT, 1)
void counter_kernel(const float* __restrict__ boxes,   // (n,4,64)
                    const float* __restrict__ attn,    // (n,64)
                    const float* __restrict__ fw,      // (16,17)
                    float* __restrict__ out)           // (n,11)
{
    extern __shared__ char smem[];
    const int tid  = threadIdx.x;
    const int bi   = blockIdx.x;
    const int lane = tid & 31;
    const int wid  = tid >> 5;
    const unsigned FULL = 0xffffffffu;

    float*  dsT    = (float*)(smem + OFF_DST);
    float*  sim    = (float*)(smem + OFF_SIM);
    float*  Am     = (float*)(smem + OFF_AM);
    float2* tab    = (float2*)(smem + OFF_TAB);
    float*  att_s  = (float*)(smem + OFF_ATT);
    float*  area_s = (float*)(smem + OFF_AREA);
    float*  sbx1   = (float*)(smem + OFF_BX1);
    float*  sby1   = (float*)(smem + OFF_BY1);
    float*  sbx2   = (float*)(smem + OFF_BX2);
    float*  sby2   = (float*)(smem + OFF_BY2);
    float*  part   = (float*)(smem + OFF_PART);
    float*  rowinv = (float*)(smem + OFF_RINV);
    float*  wredA  = (float*)(smem + OFF_WRA);
    float*  wredB  = (float*)(smem + OFF_WRB);

    // Fused address constants for the (cold) packed tables.
    const uint32_t lrep = (uint32_t)(tid & 15);
    const uint32_t C2_6 = (OFF_T6  + lrep * 8u  + 128u) - 0xA0000000u;
    const uint32_t C2_5 = (OFF_T5  + lrep * 8u  + 128u) - 0xA0000000u;
    const uint32_t C403 = (OFF_T03 + lrep * 16u + 256u) - 0x40000000u;
    const uint32_t C414 = (OFF_T14 + lrep * 16u + 256u) - 0x40000000u;

    // ---- Phase 0: serial proven table build (threads 0..7) + input loads ----
    if (tid < 8) {
        const int fn = tid;
        float w[NPW + 1];
        float s = 0.0f;
        #pragma unroll
        for (int i = 0; i <= NPW; i++) { w[i] = fabsf(fw[fn * 17 + i]); s += w[i]; }
        #pragma unroll
        for (int i = 0; i <= NPW; i++) w[i] = w[i] / s;
        float c = 0.0f;
        #pragma unroll
        for (int i = 0; i <= NPW; i++) {
            c += w[i];
            float wn = w[(i + 1 <= NPW) ? (i + 1) : NPW];
            tab[fn * 17 + i] = make_float2(c, wn);
        }
    }
    if (wid >= 8 && wid < 10) {
        const int j = tid - 256;
        att_s[j] = attn[bi * M + j];
        float x1 = boxes[(bi * 4 + 0) * M + j];
        float y1 = boxes[(bi * 4 + 1) * M + j];
        float x2 = boxes[(bi * 4 + 2) * M + j];
        float y2 = boxes[(bi * 4 + 3) * M + j];
        sbx1[j] = x1; sby1[j] = y1; sbx2[j] = x2; sby2[j] = y2;
        area_s[j] = fmaxf(x2 - x1, 0.0f) * fmaxf(y2 - y1, 0.0f);
    }
    __syncthreads();

    // ---- Phase 1a: derive packed, 16x lane-replicated cold tables ----
    if (tid < 19 * 16) {
        const uint32_t slot = (uint32_t)(tid >> 4);
        const uint32_t rep  = (uint32_t)(tid & 15);
        float2 e0 = fused_entry(tab + 0 * 17, slot);
        float2 e3 = fused_entry(tab + 3 * 17, slot);
        *(float4*)(smem + OFF_T03 + slot * 256u + rep * 16u) =
            make_float4(e0.x, 16.0f * e0.y, e3.x, 16.0f * e3.y);
        float2 e1 = fused_entry(tab + 1 * 17, slot);
        float2 e4 = fused_entry(tab + 4 * 17, slot);
        *(float4*)(smem + OFF_T14 + slot * 256u + rep * 16u) =
            make_float4(e1.x, 16.0f * e1.y, e4.x, 16.0f * e4.y);
        float2 e5 = fused_entry(tab + 5 * 17, slot);
        *(float2*)(smem + OFF_T5 + slot * 128u + rep * 8u) =
            make_float2(e5.x, 16.0f * e5.y);
        float2 e6 = fused_entry(tab + 6 * 17, slot);
        *(float2*)(smem + OFF_T6 + slot * 128u + rep * 8u) =
            make_float2(e6.x, 16.0f * e6.y);
        if (rep == 0) {
            float2 e7 = fused_entry(tab + 7 * 17, slot);
            *(float2*)(smem + OFF_T7 + slot * 8u) = make_float2(e7.x, 16.0f * e7.y);
        }
    }

    // ---- Phase 1b: hot f2 table into warp registers ----
    // Lane n (0..16) holds segment n; lanes 17..30 hold n=16; lane 31 holds
    // the n=-1 branch. Shuffle index = raw magic bits.
    float shU0, shT1;
    {
        int slot = (lane == 31) ? 0 : ((lane <= 16) ? (lane + 1) : 17);
        float2 e2 = fused_entry(tab + 2 * 17, slot);
        shU0 = fmaf(16.0f, e2.y, e2.x);   // value at d = 0 on segment n
        shT1 = e2.y;                      // per-unit-d slope
    }
    __syncthreads();

    // ---- Phase 2: SYMMETRIC pair sweep (r<=c), 2080 pairs ----
    // Mirror-stores both triangles of Am and dsT; dconf weighted 2x off-diag.
    float dconf = 0.0f;
    {
        #pragma unroll
        for (int q = 0; q < 3; q++) {
            if (q == 2 && tid >= NPAIRS2 - 2048) break;   // tail: 32 threads
            int p = tid + 1024 * q;
            // diagonal-major decode incl. d=0: cum(d) = d*(129-d)/2,
            // disc = (129-2d)^2 at boundaries -> __fsqrt_rn exact.
            float disc = 16641.0f - 8.0f * (float)p;
            int d = (int)((129.0f - __fsqrt_rn(disc)) * 0.5f);
            d = (d < 0) ? 0 : ((d > 63) ? 63 : d);
            int i = p - ((d * (129 - d)) >> 1);
            i = (i < 0) ? 0 : ((i > 63 - d) ? (63 - d) : i);
            const int k = i + d;

            float atti = att_s[i], attk = att_s[k];
            float rel = atti * attk;
            uint32_t zb0 = magic_bits(__fmaf_rn(rel, 16.0f, -0.5f));
            float4 v03 = *(const float4*)(smem + (zb0 * 256u + C403));
            float f0v = fmaf(rel, v03.y, v03.x);
            float f3v = fmaf(rel, v03.w, v03.z);

            float ix = fminf(sbx2[i], sbx2[k]) - fmaxf(sbx1[i], sbx1[k]);
            float iy = fminf(sby2[i], sby2[k]) - fmaxf(sby1[i], sby1[k]);
            ix = fmaxf(ix, 0.0f); iy = fmaxf(iy, 0.0f);
            float inter = ix * iy;
            float den   = area_s[i] + area_s[k] - inter + 1e-12f;
            float dist  = 1.0f - inter / den;

            uint32_t zb1 = magic_bits(__fmaf_rn(dist, 16.0f, -0.5f));
            float4 v14 = *(const float4*)(smem + (zb1 * 256u + C414));
            float f1v = fmaf(dist, v14.y, v14.x);
            float f4v = fmaf(dist, v14.w, v14.z);
            float2 v6 = *(const float2*)(smem + (zb1 * 128u + C2_6));
            float f6v = fmaf(dist, v6.y, v6.x);

            float Av  = f0v * f1v;
            float dsv = 16.0f * (f3v * f4v);
            Am[i * M + k] = Av;
            Am[k * M + i] = Av;
            dsT[k * DSTR + i] = dsv;
            dsT[i * DSTR + k] = dsv;
            dconf += ((d == 0) ? 1.0f : 2.0f) * fabsf(f6v - 0.5f);
        }
    }

    float attconf = 0.0f;
    if (tid < M) {
        float x = att_s[tid];
        uint32_t zb = magic_bits(__fmaf_rn(x, 16.0f, -0.5f));
        float2 v = *(const float2*)(smem + (zb * 128u + C2_5));
        attconf = fabsf(fmaf(x, v.y, v.x) - 0.5f);
    }

    // sim diagonal: f2(1)^65; csum2[16] = shU0 @ lane 16
    if (tid < M) {
        float cv = __shfl_sync(FULL, shU0, 16);
        float c2 = cv * cv, c4 = c2 * c2, c8 = c4 * c4;
        float c16 = c8 * c8, c32 = c16 * c16, c64 = c32 * c32;
        sim[tid * M + tid] = c64 * cv;
    }
    __syncthreads();

    // ---- Phase 3: hot m^3 loop; 2016 symmetric pairs, 2/thread ----
    int jj[PPT], kk[PPT];
    const float *pj[PPT], *pk[PPT];
    #pragma unroll
    for (int q = 0; q < PPT; q++) {
        int p = tid + NT * q;
        float disc = fmaxf(16129.0f - 8.0f * (float)p, 0.0f);
        int d = (int)((129.0f - __fsqrt_rn(disc)) * 0.5f);
        d = (d < 1) ? 1 : ((d > 63) ? 63 : d);
        int j = p - (((d - 1) * (128 - d)) >> 1);
        j = (j < 0) ? 0 : ((j > 63 - d) ? (63 - d) : j);
        jj[q] = j; kk[q] = j + d;
        pj[q] = dsT + j * DSTR;
        pk[q] = dsT + (j + d) * DSTR;
    }

    float prod[PPT] = {1.0f, 1.0f};

    #pragma unroll 2
    for (int lb = 0; lb < M; lb += 4) {
        #pragma unroll
        for (int q = 0; q < PPT; q++) {
            float4 a = *(const float4*)(pj[q] + lb);
            float4 b = *(const float4*)(pk[q] + lb);

            float d0 = fabsf(a.x - b.x);
            float d1 = fabsf(a.y - b.y);
            float d2 = fabsf(a.z - b.z);
            float d3 = fabsf(a.w - b.w);

            int z0 = (int)magic_bits(15.5f - d0);
            int z1 = (int)magic_bits(15.5f - d1);
            int z2 = (int)magic_bits(15.5f - d2);
            int z3 = (int)magic_bits(15.5f - d3);

            float u0 = __shfl_sync(FULL, shU0, z0);
            float t0 = __shfl_sync(FULL, shT1, z0);
            float u1 = __shfl_sync(FULL, shU0, z1);
            float t1 = __shfl_sync(FULL, shT1, z1);
            float u2 = __shfl_sync(FULL, shU0, z2);
            float t2 = __shfl_sync(FULL, shT1, z2);
            float u3 = __shfl_sync(FULL, shU0, z3);
            float t3 = __shfl_sync(FULL, shT1, z3);

            float e0 = fmaf(-d0, t0, u0);
            float e1 = fmaf(-d1, t1, u1);
            float e2 = fmaf(-d2, t2, u2);
            float e3 = fmaf(-d3, t3, u3);

            prod[q] *= (e0 * e1) * (e2 * e3);
        }
    }

    #pragma unroll
    for (int q = 0; q < PPT; q++) {
        const int j = jj[q], k = kk[q];
        float y16 = 16.0f * fabsf(att_s[j] - att_s[k]);   // exact x16
        int zb = (int)magic_bits(15.5f - y16);
        float uu = __shfl_sync(FULL, shU0, zb);
        float tt = __shfl_sync(FULL, shT1, zb);
        float sv = prod[q] * fmaf(-y16, tt, uu);
        sim[j * M + k] = sv;
        sim[k * M + j] = sv;
    }
    __syncthreads();

    // ---- Phase 4: row sums (column-wise, conflict-free) -> rowinv ----
    const int c = tid & 63;
    const int g = tid >> 6;
    {
        float s = 0.0f;
        #pragma unroll
        for (int it = 0; it < 4; it++)
            s += sim[(g + NG * it) * M + c];
        part[g * M + c] = s;
    }
    __syncthreads();
    if (tid < M) {
        float rs = 0.0f;
        #pragma unroll
        for (int gg = 0; gg < NG; gg++) rs += part[gg * M + tid];
        rowinv[tid] = 1.0f / rs;
    }
    __syncthreads();

    // ---- Phase 5: score accumulation (Am reused) ----
    float accA = 0.0f;
    #pragma unroll
    for (int it = 0; it < 4; it++) {
        const int r = g + NG * it;
        accA += Am[r * M + c] * rowinv[r];
    }
    accA *= rowinv[c];

    float corr = 0.0f;
    if (tid < M) {
        float a = att_s[tid];
        float aa = a * a;
        uint32_t zb = magic_bits(__fmaf_rn(aa, 16.0f, -0.5f));
        float4 v03 = *(const float4*)(smem + (zb * 256u + C403));
        corr = fmaf(aa, v03.y, v03.x) * rowinv[tid];
    }

    float ra  = accA + corr;
    float rbv = dconf * (1.0f / 4096.0f) + attconf * (1.0f / 64.0f);
    #pragma unroll
    for (int off = 16; off > 0; off >>= 1) {
        ra  += __shfl_down_sync(FULL, ra,  off);
        rbv += __shfl_down_sync(FULL, rbv, off);
    }
    if (lane == 0) { wredA[wid] = ra; wredB[wid] = rbv; }
    __syncthreads();

    // ---- Phase 6: score -> one-hot * conf ----
    if (tid == 0) {
        float S = 0.0f, B = 0.0f;
        #pragma unroll
        for (int i = 0; i < NW; i++) { S += wredA[i]; B += wredB[i]; }

        float score = sqrtf(S + 1e-20f);
        uint32_t zb = magic_bits(__fmaf_rn(B, 16.0f, -0.5f));
        int slot = (int)(zb - 0x4B3FFFFFu);
        slot = (slot < 0) ? 0 : ((slot > 18) ? 18 : slot);
        float2 v7 = *(const float2*)(smem + OFF_T7 + (uint32_t)slot * 8u);
        float conf = fmaf(B, v7.y, v7.x);

        float sc = fminf(fmaxf(score, 0.0f), (float)OBJ);
        int   i0 = (int)sc;
        float fr = sc - floorf(sc);
        int   i1 = (i0 + 1 <= OBJ) ? (i0 + 1) : OBJ;

        #pragma unroll
        for (int o = 0; o <= OBJ; o++) {
            float v = 0.0f;
            if (o == i0) v += (1.0f - fr);
            if (o == i1) v += fr;
            out[bi * (OBJ + 1) + o] = conf * v;
        }
    }
}

extern "C" void kernel_launch(void* const* d_in, const int* in_sizes, int n_in,
                              void* d_out, int out_size) {
    const float* boxes = (const float*)d_in[0];   // (n,4,64)
    const float* attn  = (const float*)d_in[1];   // (n,64)
    const float* fwts  = (const float*)d_in[2];   // (16,17)
    float* out = (float*)d_out;                   // (n,11)

    cudaFuncSetAttribute(counter_kernel,
                         cudaFuncAttributeMaxDynamicSharedMemorySize, SMEM_TOTAL);

    const int n = in_sizes[1] / M;                // 128
    counter_kernel<<<n, NT, SMEM_TOTAL>>>(boxes, attn, fwts, out);
}

// round 12
// speedup vs baseline: 1.0851x; 1.0851x over previous
#include <cuda_runtime.h>
#include <cuda_bf16.h>
#include <stdint.h>

#define NPW 16
#define M   64
#define NT  1024           // 32 warps, 8/SMSP
#define NW  (NT / 32)
#define NG  16             // row groups for m^2 phases: 16 groups x 4 rows
#define OBJ 10
#define DSTR 68            // dsT row stride (floats); 68*4 % 16 == 0, 68 % 32 == 4

#define MAGIC 12582912.0f  // 1.5*2^23; bits(MAGIC + n) = 0x4B400000 + n

// Dynamic shared memory layout (bytes); all offsets 16B-aligned
#define OFF_DST   0u          // dsT[j*68 + l], pre-scaled by 16      (17408)
#define OFF_SIM   17408u      // (16384)
#define OFF_AM    33792u      // (16384)
#define OFF_T03   50176u      // float4[19*16]  f0 .xy / f3 .zw       (4864)
#define OFF_T14   55040u      // float4[19*16]  f1 .xy / f4 .zw       (4864)
#define OFF_T6    62336u      // float2[19*16]                        (2432)
#define OFF_T5    64768u      // float2[19*16]                        (2432)
#define OFF_T7    67200u      // float2[19] + pad                     (160)
#define OFF_TAB   67360u      // float2[8*17] (csum, w_next)          (1088)
#define OFF_ATT   68448u
#define OFF_AREA  68704u
#define OFF_BX1   68960u
#define OFF_BY1   69216u
#define OFF_BX2   69472u
#define OFF_BY2   69728u
#define OFF_PART  69984u      // NG*64*4 = 4096
#define OFF_RINV  74080u
#define OFF_WRA   74336u      // 32 floats
#define OFF_WRB   74464u      // 32 floats
#define SMEM_TOTAL 74592u

// Protected magic-add: __fadd_rn is never merged/reassociated, so the -0.5
// bias cannot be refolded into MAGIC by fast-math (the R5/R6 bug).
__device__ __forceinline__ uint32_t magic_bits(float t) {
    return __float_as_uint(__fadd_rn(t, MAGIC));
}

// Fused-table entry for slot = n+1 (n = -1..17):
//   val(x) = T0 + (16x)*T1 on segment n, T0 = csum[n] - n*w_next, T1 = w_next.
//   slot 0 (n=-1) encodes the reference's x<0 branch.
__device__ __forceinline__ float2 fused_entry(const float2* __restrict__ t, int slot) {
    if (slot == 0) {
        float cs0 = t[0].x, w1 = t[0].y;
        return make_float2(cs0 + w1, w1);
    }
    int n = slot - 1; if (n > 16) n = 16;
    float2 v = t[n];
    return make_float2(fmaf(-(float)n, v.y, v.x), v.y);
}

__global__ __launch_bounds__(NT, 1)
void counter_kernel(const float* __restrict__ boxes,   // (n,4,64)
                    const float* __restrict__ attn,    // (n,64)
                    const float* __restrict__ fw,      // (16,17)
                    float* __restrict__ out)           // (n,11)
{
    extern __shared__ char smem[];
    const int tid  = threadIdx.x;
    const int bi   = blockIdx.x;
    const int lane = tid & 31;
    const int wid  = tid >> 5;
    const unsigned FULL = 0xffffffffu;

    float*  dsT    = (float*)(smem + OFF_DST);
    float*  sim    = (float*)(smem + OFF_SIM);
    float*  Am     = (float*)(smem + OFF_AM);
    float2* tab    = (float2*)(smem + OFF_TAB);
    float*  att_s  = (float*)(smem + OFF_ATT);
    float*  area_s = (float*)(smem + OFF_AREA);
    float*  sbx1   = (float*)(smem + OFF_BX1);
    float*  sby1   = (float*)(smem + OFF_BY1);
    float*  sbx2   = (float*)(smem + OFF_BX2);
    float*  sby2   = (float*)(smem + OFF_BY2);
    float*  part   = (float*)(smem + OFF_PART);
    float*  rowinv = (float*)(smem + OFF_RINV);
    float*  wredA  = (float*)(smem + OFF_WRA);
    float*  wredB  = (float*)(smem + OFF_WRB);

    // Fused address constants for the (cold) packed tables.
    const uint32_t lrep = (uint32_t)(tid & 15);
    const uint32_t C2_6 = (OFF_T6  + lrep * 8u  + 128u) - 0xA0000000u;
    const uint32_t C2_5 = (OFF_T5  + lrep * 8u  + 128u) - 0xA0000000u;
    const uint32_t C403 = (OFF_T03 + lrep * 16u + 256u) - 0x40000000u;
    const uint32_t C414 = (OFF_T14 + lrep * 16u + 256u) - 0x40000000u;

    // ---- Phase 0: serial proven table build (threads 0..7) + input loads ----
    if (tid < 8) {
        const int fn = tid;
        float w[NPW + 1];
        float s = 0.0f;
        #pragma unroll
        for (int i = 0; i <= NPW; i++) { w[i] = fabsf(fw[fn * 17 + i]); s += w[i]; }
        #pragma unroll
        for (int i = 0; i <= NPW; i++) w[i] = w[i] / s;
        float c = 0.0f;
        #pragma unroll
        for (int i = 0; i <= NPW; i++) {
            c += w[i];
            float wn = w[(i + 1 <= NPW) ? (i + 1) : NPW];
            tab[fn * 17 + i] = make_float2(c, wn);
        }
    }
    if (wid >= 8 && wid < 10) {
        const int j = tid - 256;
        att_s[j] = attn[bi * M + j];
        float x1 = boxes[(bi * 4 + 0) * M + j];
        float y1 = boxes[(bi * 4 + 1) * M + j];
        float x2 = boxes[(bi * 4 + 2) * M + j];
        float y2 = boxes[(bi * 4 + 3) * M + j];
        sbx1[j] = x1; sby1[j] = y1; sbx2[j] = x2; sby2[j] = y2;
        area_s[j] = fmaxf(x2 - x1, 0.0f) * fmaxf(y2 - y1, 0.0f);
    }
    __syncthreads();

    // ---- Phase 1a: derive packed, 16x lane-replicated cold tables ----
    if (tid < 19 * 16) {
        const uint32_t slot = (uint32_t)(tid >> 4);
        const uint32_t rep  = (uint32_t)(tid & 15);
        float2 e0 = fused_entry(tab + 0 * 17, slot);
        float2 e3 = fused_entry(tab + 3 * 17, slot);
        *(float4*)(smem + OFF_T03 + slot * 256u + rep * 16u) =
            make_float4(e0.x, 16.0f * e0.y, e3.x, 16.0f * e3.y);
        float2 e1 = fused_entry(tab + 1 * 17, slot);
        float2 e4 = fused_entry(tab + 4 * 17, slot);
        *(float4*)(smem + OFF_T14 + slot * 256u + rep * 16u) =
            make_float4(e1.x, 16.0f * e1.y, e4.x, 16.0f * e4.y);
        float2 e5 = fused_entry(tab + 5 * 17, slot);
        *(float2*)(smem + OFF_T5 + slot * 128u + rep * 8u) =
            make_float2(e5.x, 16.0f * e5.y);
        float2 e6 = fused_entry(tab + 6 * 17, slot);
        *(float2*)(smem + OFF_T6 + slot * 128u + rep * 8u) =
            make_float2(e6.x, 16.0f * e6.y);
        if (rep == 0) {
            float2 e7 = fused_entry(tab + 7 * 17, slot);
            *(float2*)(smem + OFF_T7 + slot * 8u) = make_float2(e7.x, 16.0f * e7.y);
        }
    }

    // ---- Phase 1b: hot f2 table into warp registers ----
    // Lane n (0..16) holds segment n; lanes 17..30 hold n=16; lane 31 holds
    // the n=-1 branch. Shuffle index = raw magic bits.
    float shU0, shT1;
    {
        int slot = (lane == 31) ? 0 : ((lane <= 16) ? (lane + 1) : 17);
        float2 e2 = fused_entry(tab + 2 * 17, slot);
        shU0 = fmaf(16.0f, e2.y, e2.x);   // value at d = 0 on segment n
        shT1 = e2.y;                      // per-unit-d slope
    }
    __syncthreads();

    // ---- Phase 2: ds16 (transposed), Am = f0*f1, dconf, attconf, sim diag ----
    const int c = tid & 63;
    const int g = tid >> 6;                        // 0..15: 4 rows each
    const float attc = att_s[c];

    float attconf = 0.0f;
    if (tid < M) {
        float x = att_s[tid];
        uint32_t zb = magic_bits(__fmaf_rn(x, 16.0f, -0.5f));
        float2 v = *(const float2*)(smem + (zb * 128u + C2_5));
        attconf = fabsf(fmaf(x, v.y, v.x) - 0.5f);
    }

    float dconf = 0.0f;
    {
        const float x1c = sbx1[c], y1c = sby1[c], x2c = sbx2[c], y2c = sby2[c];
        const float arc = area_s[c];
        #pragma unroll
        for (int it = 0; it < 4; it++) {
            const int r = g + NG * it;
            float rel = att_s[r] * attc;
            uint32_t zb0 = magic_bits(__fmaf_rn(rel, 16.0f, -0.5f));
            float4 v03 = *(const float4*)(smem + (zb0 * 256u + C403));
            float f0v = fmaf(rel, v03.y, v03.x);
            float f3v = fmaf(rel, v03.w, v03.z);

            float ix = fminf(sbx2[r], x2c) - fmaxf(sbx1[r], x1c);
            float iy = fminf(sby2[r], y2c) - fmaxf(sby1[r], y1c);
            ix = fmaxf(ix, 0.0f); iy = fmaxf(iy, 0.0f);
            float inter = ix * iy;
            float den   = area_s[r] + arc - inter + 1e-12f;
            float dist  = 1.0f - inter / den;

            uint32_t zb1 = magic_bits(__fmaf_rn(dist, 16.0f, -0.5f));
            float4 v14 = *(const float4*)(smem + (zb1 * 256u + C414));
            float f1v = fmaf(dist, v14.y, v14.x);
            float f4v = fmaf(dist, v14.w, v14.z);
            float2 v6 = *(const float2*)(smem + (zb1 * 128u + C2_6));
            float f6v = fmaf(dist, v6.y, v6.x);

            Am[r * M + c]     = f0v * f1v;
            dsT[c * DSTR + r] = 16.0f * (f3v * f4v);
            dconf += fabsf(f6v - 0.5f);
        }
    }

    // sim diagonal: f2(1)^65; csum2[16] = shU0 @ lane 16
    if (tid < M) {
        float cv = __shfl_sync(FULL, shU0, 16);
        float c2 = cv * cv, c4 = c2 * c2, c8 = c4 * c4;
        float c16 = c8 * c8, c32 = c16 * c16, c64 = c32 * c32;
        sim[tid * M + tid] = c64 * cv;
    }
    __syncthreads();

    // ---- Phase 3: hot m^3 loop; j-sharing slots ----
    // Slot = (j, k1=j+1+2o, k2=k1+1): two pairs share row j -> 3 row loads.
    // Enumerated by (o, j): cum(o) = o*(64-o); exactly 1024 slots.
    // Consecutive lanes -> consecutive j AND k -> stride-68 conflict-free.
    int sj, sk1, sk2;
    {
        int p = tid;
        float s = __fsqrt_rn((float)(1024 - p));   // exact at boundaries
        int si = (int)s;
        int o = 32 - (si + (((float)si < s) ? 1 : 0));   // 32 - ceil(s)
        o = (o < 0) ? 0 : ((o > 31) ? 31 : o);
        // bounded corrections
        if (p <  o * (64 - o) && o > 0)  o--;
        if (p >= (o + 1) * (63 - o) && o < 31) o++;
        if (p <  o * (64 - o) && o > 0)  o--;
        int j = p - o * (64 - o);
        int jmax = 62 - 2 * o;
        j = (j < 0) ? 0 : ((j > jmax) ? jmax : j);
        sj  = j;
        sk1 = j + 1 + 2 * o;                // <= 63
        sk2 = (sk1 < 63) ? (sk1 + 1) : 63;  // last slot of odd row: duplicate
    }
    const float* pj  = dsT + sj  * DSTR;
    const float* pk1 = dsT + sk1 * DSTR;
    const float* pk2 = dsT + sk2 * DSTR;

    float prod1 = 1.0f, prod2 = 1.0f;

    #pragma unroll 2
    for (int lb = 0; lb < M; lb += 4) {
        float4 a  = *(const float4*)(pj  + lb);
        float4 b  = *(const float4*)(pk1 + lb);
        float4 cc = *(const float4*)(pk2 + lb);

        float d0 = fabsf(a.x - b.x);
        float d1 = fabsf(a.y - b.y);
        float d2 = fabsf(a.z - b.z);
        float d3 = fabsf(a.w - b.w);
        float e0 = fabsf(a.x - cc.x);
        float e1 = fabsf(a.y - cc.y);
        float e2 = fabsf(a.z - cc.z);
        float e3 = fabsf(a.w - cc.w);

        int zd0 = (int)magic_bits(15.5f - d0);
        int zd1 = (int)magic_bits(15.5f - d1);
        int zd2 = (int)magic_bits(15.5f - d2);
        int zd3 = (int)magic_bits(15.5f - d3);
        int ze0 = (int)magic_bits(15.5f - e0);
        int ze1 = (int)magic_bits(15.5f - e1);
        int ze2 = (int)magic_bits(15.5f - e2);
        int ze3 = (int)magic_bits(15.5f - e3);

        float ud0 = __shfl_sync(FULL, shU0, zd0);
        float td0 = __shfl_sync(FULL, shT1, zd0);
        float ud1 = __shfl_sync(FULL, shU0, zd1);
        float td1 = __shfl_sync(FULL, shT1, zd1);
        float ud2 = __shfl_sync(FULL, shU0, zd2);
        float td2 = __shfl_sync(FULL, shT1, zd2);
        float ud3 = __shfl_sync(FULL, shU0, zd3);
        float td3 = __shfl_sync(FULL, shT1, zd3);
        float ue0 = __shfl_sync(FULL, shU0, ze0);
        float te0 = __shfl_sync(FULL, shT1, ze0);
        float ue1 = __shfl_sync(FULL, shU0, ze1);
        float te1 = __shfl_sync(FULL, shT1, ze1);
        float ue2 = __shfl_sync(FULL, shU0, ze2);
        float te2 = __shfl_sync(FULL, shT1, ze2);
        float ue3 = __shfl_sync(FULL, shU0, ze3);
        float te3 = __shfl_sync(FULL, shT1, ze3);

        float f0 = fmaf(-d0, td0, ud0);
        float f1 = fmaf(-d1, td1, ud1);
        float f2 = fmaf(-d2, td2, ud2);
        float f3 = fmaf(-d3, td3, ud3);
        float g0 = fmaf(-e0, te0, ue0);
        float g1 = fmaf(-e1, te1, ue1);
        float g2 = fmaf(-e2, te2, ue2);
        float g3 = fmaf(-e3, te3, ue3);

        prod1 *= (f0 * f1) * (f2 * f3);
        prod2 *= (g0 * g1) * (g2 * g3);
    }

    {
        float attj = att_s[sj];
        float y1 = 16.0f * fabsf(attj - att_s[sk1]);
        float y2 = 16.0f * fabsf(attj - att_s[sk2]);
        int zb1 = (int)magic_bits(15.5f - y1);
        int zb2 = (int)magic_bits(15.5f - y2);
        float u1 = __shfl_sync(FULL, shU0, zb1);
        float t1 = __shfl_sync(FULL, shT1, zb1);
        float u2 = __shfl_sync(FULL, shU0, zb2);
        float t2 = __shfl_sync(FULL, shT1, zb2);
        float sv1 = prod1 * fmaf(-y1, t1, u1);
        float sv2 = prod2 * fmaf(-y2, t2, u2);
        sim[sj  * M + sk1] = sv1;
        sim[sk1 * M + sj ] = sv1;
        sim[sj  * M + sk2] = sv2;
        sim[sk2 * M + sj ] = sv2;
    }
    __syncthreads();

    // ---- Phase 4: row sums (column-wise, conflict-free) -> rowinv ----
    {
        float s = 0.0f;
        #pragma unroll
        for (int it = 0; it < 4; it++)
            s += sim[(g + NG * it) * M + c];
        part[g * M + c] = s;
    }
    __syncthreads();
    if (tid < M) {
        float rs = 0.0f;
        #pragma unroll
        for (int gg = 0; gg < NG; gg++) rs += part[gg * M + tid];
        rowinv[tid] = 1.0f / rs;
    }
    __syncthreads();

    // ---- Phase 5: score accumulation (Am reused) ----
    float accA = 0.0f;
    #pragma unroll
    for (int it = 0; it < 4; it++) {
        const int r = g + NG * it;
        accA += Am[r * M + c] * rowinv[r];
    }
    accA *= rowinv[c];

    float corr = 0.0f;
    if (tid < M) {
        float a = att_s[tid];
        float aa = a * a;
        uint32_t zb = magic_bits(__fmaf_rn(aa, 16.0f, -0.5f));
        float4 v03 = *(const float4*)(smem + (zb * 256u + C403));
        corr = fmaf(aa, v03.y, v03.x) * rowinv[tid];
    }

    float ra  = accA + corr;
    float rbv = dconf * (1.0f / 4096.0f) + attconf * (1.0f / 64.0f);
    #pragma unroll
    for (int off = 16; off > 0; off >>= 1) {
        ra  += __shfl_down_sync(FULL, ra,  off);
        rbv += __shfl_down_sync(FULL, rbv, off);
    }
    if (lane == 0) { wredA[wid] = ra; wredB[wid] = rbv; }
    __syncthreads();

    // ---- Phase 6: score -> one-hot * conf ----
    if (tid == 0) {
        float S = 0.0f, B = 0.0f;
        #pragma unroll
        for (int i = 0; i < NW; i++) { S += wredA[i]; B += wredB[i]; }

        float score = sqrtf(S + 1e-20f);
        uint32_t zb = magic_bits(__fmaf_rn(B, 16.0f, -0.5f));
        int slot = (int)(zb - 0x4B3FFFFFu);
        slot = (slot < 0) ? 0 : ((slot > 18) ? 18 : slot);
        float2 v7 = *(const float2*)(smem + OFF_T7 + (uint32_t)slot * 8u);
        float conf = fmaf(B, v7.y, v7.x);

        float sc = fminf(fmaxf(score, 0.0f), (float)OBJ);
        int   i0 = (int)sc;
        float fr = sc - floorf(sc);
        int   i1 = (i0 + 1 <= OBJ) ? (i0 + 1) : OBJ;

        #pragma unroll
        for (int o = 0; o <= OBJ; o++) {
            float v = 0.0f;
            if (o == i0) v += (1.0f - fr);
            if (o == i1) v += fr;
            out[bi * (OBJ + 1) + o] = conf * v;
        }
    }
}

extern "C" void kernel_launch(void* const* d_in, const int* in_sizes, int n_in,
                              void* d_out, int out_size) {
    const float* boxes = (const float*)d_in[0];   // (n,4,64)
    const float* attn  = (const float*)d_in[1];   // (n,64)
    const float* fwts  = (const float*)d_in[2];   // (16,17)
    float* out = (float*)d_out;                   // (n,11)

    cudaFuncSetAttribute(counter_kernel,
                         cudaFuncAttributeMaxDynamicSharedMemorySize, SMEM_TOTAL);

    const int n = in_sizes[1] / M;                // 128
    counter_kernel<<<n, NT, SMEM_TOTAL>>>(boxes, attn, fwts, out);
}

// round 13
// speedup vs baseline: 1.1134x; 1.0260x over previous
#include <cuda_runtime.h>
#include <cuda_bf16.h>
#include <stdint.h>

#define NPW 16
#define M   64
#define NT  1024           // 32 warps, 8/SMSP
#define NW  (NT / 32)
#define NG  16             // row groups for m^2 phases: 16 groups x 4 rows
#define OBJ 10
#define DSTR 68            // dsT row stride (floats)

#define MAGIC 12582912.0f  // 1.5*2^23; bits(MAGIC + m) = 0x4B400000 + m

// Dynamic shared memory layout (bytes); all offsets 16B-aligned
#define OFF_DST   0u          // dsT[j*68 + l], pre-scaled by 16, in [0,16)  (17408)
#define OFF_SIM   17408u      // (16384)
#define OFF_AM    33792u      // (16384)
#define OFF_T03   50176u      // float4[19*16]  f0 .xy / f3 .zw       (4864)
#define OFF_T14   55040u      // float4[19*16]  f1 .xy / f4 .zw       (4864)
#define OFF_T6    62336u      // float2[19*16]                        (2432)
#define OFF_T5    64768u      // float2[19*16]                        (2432)
#define OFF_T7    67200u      // float2[19] + pad                     (160)
#define OFF_TAB   67360u      // float2[8*17] (csum, w_next)          (1088)
#define OFF_ATT   68448u
#define OFF_AREA  68704u
#define OFF_BX1   68960u
#define OFF_BY1   69216u
#define OFF_BX2   69472u
#define OFF_BY2   69728u
#define OFF_PART  69984u      // NG*64*4 = 4096
#define OFF_RINV  74080u
#define OFF_WRA   74336u      // 32 floats
#define OFF_WRB   74464u      // 32 floats
#define SMEM_TOTAL 74592u

// Protected magic-add: __fadd_rn is never merged/reassociated, so fast-math
// cannot refold bias constants into MAGIC (the R5/R6 bug).
__device__ __forceinline__ uint32_t magic_bits(float t) {
    return __float_as_uint(__fadd_rn(t, MAGIC));
}

// Fused-table entry for slot = n+1 (n = -1..17):
//   val(x) = T0 + (16x)*T1 on segment n, T0 = csum[n] - n*w_next, T1 = w_next.
//   slot 0 (n=-1) encodes the reference's x<0 branch.
__device__ __forceinline__ float2 fused_entry(const float2* __restrict__ t, int slot) {
    if (slot == 0) {
        float cs0 = t[0].x, w1 = t[0].y;
        return make_float2(cs0 + w1, w1);
    }
    int n = slot - 1; if (n > 16) n = 16;
    float2 v = t[n];
    return make_float2(fmaf(-(float)n, v.y, v.x), v.y);
}

__global__ __launch_bounds__(NT, 1)
void counter_kernel(const float* __restrict__ boxes,   // (n,4,64)
                    const float* __restrict__ attn,    // (n,64)
                    const float* __restrict__ fw,      // (16,17)
                    float* __restrict__ out)           // (n,11)
{
    extern __shared__ char smem[];
    const int tid  = threadIdx.x;
    const int bi   = blockIdx.x;
    const int lane = tid & 31;
    const int wid  = tid >> 5;
    const unsigned FULL = 0xffffffffu;

    float*  dsT    = (float*)(smem + OFF_DST);
    float*  sim    = (float*)(smem + OFF_SIM);
    float*  Am     = (float*)(smem + OFF_AM);
    float2* tab    = (float2*)(smem + OFF_TAB);
    float*  att_s  = (float*)(smem + OFF_ATT);
    float*  area_s = (float*)(smem + OFF_AREA);
    float*  sbx1   = (float*)(smem + OFF_BX1);
    float*  sby1   = (float*)(smem + OFF_BY1);
    float*  sbx2   = (float*)(smem + OFF_BX2);
    float*  sby2   = (float*)(smem + OFF_BY2);
    float*  part   = (float*)(smem + OFF_PART);
    float*  rowinv = (float*)(smem + OFF_RINV);
    float*  wredA  = (float*)(smem + OFF_WRA);
    float*  wredB  = (float*)(smem + OFF_WRB);

    // Fused address constants for the (cold) packed tables.
    const uint32_t lrep = (uint32_t)(tid & 15);
    const uint32_t C2_6 = (OFF_T6  + lrep * 8u  + 128u) - 0xA0000000u;
    const uint32_t C2_5 = (OFF_T5  + lrep * 8u  + 128u) - 0xA0000000u;
    const uint32_t C403 = (OFF_T03 + lrep * 16u + 256u) - 0x40000000u;
    const uint32_t C414 = (OFF_T14 + lrep * 16u + 256u) - 0x40000000u;

    // ---- Phase 0: serial proven table build (threads 0..7) + input loads ----
    if (tid < 8) {
        const int fn = tid;
        float w[NPW + 1];
        float s = 0.0f;
        #pragma unroll
        for (int i = 0; i <= NPW; i++) { w[i] = fabsf(fw[fn * 17 + i]); s += w[i]; }
        #pragma unroll
        for (int i = 0; i <= NPW; i++) w[i] = w[i] / s;
        float c = 0.0f;
        #pragma unroll
        for (int i = 0; i <= NPW; i++) {
            c += w[i];
            float wn = w[(i + 1 <= NPW) ? (i + 1) : NPW];
            tab[fn * 17 + i] = make_float2(c, wn);
        }
    }
    if (wid >= 8 && wid < 10) {
        const int j = tid - 256;
        att_s[j] = attn[bi * M + j];
        float x1 = boxes[(bi * 4 + 0) * M + j];
        float y1 = boxes[(bi * 4 + 1) * M + j];
        float x2 = boxes[(bi * 4 + 2) * M + j];
        float y2 = boxes[(bi * 4 + 3) * M + j];
        sbx1[j] = x1; sby1[j] = y1; sbx2[j] = x2; sby2[j] = y2;
        area_s[j] = fmaxf(x2 - x1, 0.0f) * fmaxf(y2 - y1, 0.0f);
    }
    __syncthreads();

    // ---- Phase 1a: derive packed, 16x lane-replicated cold tables ----
    if (tid < 19 * 16) {
        const uint32_t slot = (uint32_t)(tid >> 4);
        const uint32_t rep  = (uint32_t)(tid & 15);
        float2 e0 = fused_entry(tab + 0 * 17, slot);
        float2 e3 = fused_entry(tab + 3 * 17, slot);
        *(float4*)(smem + OFF_T03 + slot * 256u + rep * 16u) =
            make_float4(e0.x, 16.0f * e0.y, e3.x, 16.0f * e3.y);
        float2 e1 = fused_entry(tab + 1 * 17, slot);
        float2 e4 = fused_entry(tab + 4 * 17, slot);
        *(float4*)(smem + OFF_T14 + slot * 256u + rep * 16u) =
            make_float4(e1.x, 16.0f * e1.y, e4.x, 16.0f * e4.y);
        float2 e5 = fused_entry(tab + 5 * 17, slot);
        *(float2*)(smem + OFF_T5 + slot * 128u + rep * 8u) =
            make_float2(e5.x, 16.0f * e5.y);
        float2 e6 = fused_entry(tab + 6 * 17, slot);
        *(float2*)(smem + OFF_T6 + slot * 128u + rep * 8u) =
            make_float2(e6.x, 16.0f * e6.y);
        if (rep == 0) {
            float2 e7 = fused_entry(tab + 7 * 17, slot);
            *(float2*)(smem + OFF_T7 + slot * 8u) = make_float2(e7.x, 16.0f * e7.y);
        }
    }

    // ---- Phase 1b: SIGNED-u hot f2 table into warp registers ----
    // e(u) = f2(1 - |u|/16-scaled) is continuous piecewise-linear in
    // u = ds_j - ds_k over (-16,16): 32 integer-knot classes m = floor(u).
    // lane = m mod 32 (lanes 0..15: m=0..15, u>=0, segment n=15-m;
    //                  lanes 16..31: m=-16..-1, u<0,  segment n=m+16).
    // With u' = u - 0.5:  e = shA + u' * shB.
    float shA, shB;
    {
        int n = (lane < 16) ? (15 - lane) : (lane - 16);
        float2 e2 = fused_entry(tab + 2 * 17, n + 1);
        float U0 = fmaf(16.0f, e2.y, e2.x);       // value at d=0 on segment n
        if (lane < 16) { shA = fmaf(-0.5f, e2.y, U0); shB = -e2.y; }
        else           { shA = fmaf( 0.5f, e2.y, U0); shB =  e2.y; }
    }
    __syncthreads();

    // ---- Phase 2: ds16 (transposed, clamped to [0,16)), Am, dconf, attconf ----
    const int c = tid & 63;
    const int g = tid >> 6;                        // 0..15: 4 rows each
    const float attc = att_s[c];

    float attconf = 0.0f;
    if (tid < M) {
        float x = att_s[tid];
        uint32_t zb = magic_bits(__fmaf_rn(x, 16.0f, -0.5f));
        float2 v = *(const float2*)(smem + (zb * 128u + C2_5));
        attconf = fabsf(fmaf(x, v.y, v.x) - 0.5f);
    }

    float dconf = 0.0f;
    {
        const float x1c = sbx1[c], y1c = sby1[c], x2c = sbx2[c], y2c = sby2[c];
        const float arc = area_s[c];
        #pragma unroll
        for (int it = 0; it < 4; it++) {
            const int r = g + NG * it;
            float rel = att_s[r] * attc;
            uint32_t zb0 = magic_bits(__fmaf_rn(rel, 16.0f, -0.5f));
            float4 v03 = *(const float4*)(smem + (zb0 * 256u + C403));
            float f0v = fmaf(rel, v03.y, v03.x);
            float f3v = fmaf(rel, v03.w, v03.z);

            float ix = fminf(sbx2[r], x2c) - fmaxf(sbx1[r], x1c);
            float iy = fminf(sby2[r], y2c) - fmaxf(sby1[r], y1c);
            ix = fmaxf(ix, 0.0f); iy = fmaxf(iy, 0.0f);
            float inter = ix * iy;
            float den   = area_s[r] + arc - inter + 1e-12f;
            float dist  = 1.0f - inter / den;

            uint32_t zb1 = magic_bits(__fmaf_rn(dist, 16.0f, -0.5f));
            float4 v14 = *(const float4*)(smem + (zb1 * 256u + C414));
            float f1v = fmaf(dist, v14.y, v14.x);
            float f4v = fmaf(dist, v14.w, v14.z);
            float2 v6 = *(const float2*)(smem + (zb1 * 128u + C2_6));
            float f6v = fmaf(dist, v6.y, v6.x);

            float dsv = 16.0f * (f3v * f4v);
            dsv = fminf(fmaxf(dsv, 0.0f), 15.999999f);   // |u| < 16 strictly

            Am[r * M + c]     = f0v * f1v;
            dsT[c * DSTR + r] = dsv;
            dconf += fabsf(f6v - 0.5f);
        }
    }

    // sim diagonal: f2(1)^65; csum2[16] from the base table
    if (tid < M) {
        float cv = tab[2 * 17 + NPW].x;
        float c2 = cv * cv, c4 = c2 * c2, c8 = c4 * c4;
        float c16 = c8 * c8, c32 = c16 * c16, c64 = c32 * c32;
        sim[tid * M + tid] = c64 * cv;
    }
    __syncthreads();

    // ---- Phase 3: hot m^3 loop; j-sharing slots, software-pipelined ----
    // Slot = (j, k1=j+1+2o, k2=k1+1): two pairs share row j -> 3 row loads.
    // Enumerated by (o, j): cum(o) = o*(64-o); exactly 1024 slots.
    int sj, sk1, sk2;
    {
        int p = tid;
        float s = __fsqrt_rn((float)(1024 - p));   // exact at boundaries
        int si = (int)s;
        int o = 32 - (si + (((float)si < s) ? 1 : 0));   // 32 - ceil(s)
        o = (o < 0) ? 0 : ((o > 31) ? 31 : o);
        if (p <  o * (64 - o) && o > 0)  o--;
        if (p >= (o + 1) * (63 - o) && o < 31) o++;
        if (p <  o * (64 - o) && o > 0)  o--;
        int j = p - o * (64 - o);
        int jmax = 62 - 2 * o;
        j = (j < 0) ? 0 : ((j > jmax) ? jmax : j);
        sj  = j;
        sk1 = j + 1 + 2 * o;                // <= 63
        sk2 = (sk1 < 63) ? (sk1 + 1) : 63;  // last slot of odd row: duplicate
    }
    const float* pj  = dsT + sj  * DSTR;
    const float* pk1 = dsT + sk1 * DSTR;
    const float* pk2 = dsT + sk2 * DSTR;

    float prod1 = 1.0f, prod2 = 1.0f;

    float4 a0 = *(const float4*)(pj);
    float4 b0 = *(const float4*)(pk1);
    float4 c0 = *(const float4*)(pk2);

    #pragma unroll 4
    for (int lb = 0; lb < M; lb += 4) {
        float4 a1, b1, c1;
        if (lb + 4 < M) {
            a1 = *(const float4*)(pj  + lb + 4);
            b1 = *(const float4*)(pk1 + lb + 4);
            c1 = *(const float4*)(pk2 + lb + 4);
        }

        // am = a - 0.5 (shared by both pairs)
        float am0 = a0.x - 0.5f, am1 = a0.y - 0.5f;
        float am2 = a0.z - 0.5f, am3 = a0.w - 0.5f;

        float u0 = am0 - b0.x, u1 = am1 - b0.y, u2 = am2 - b0.z, u3 = am3 - b0.w;
        float v0 = am0 - c0.x, v1 = am1 - c0.y, v2 = am2 - c0.z, v3 = am3 - c0.w;

        int zu0 = (int)magic_bits(u0);
        int zu1 = (int)magic_bits(u1);
        int zu2 = (int)magic_bits(u2);
        int zu3 = (int)magic_bits(u3);
        int zv0 = (int)magic_bits(v0);
        int zv1 = (int)magic_bits(v1);
        int zv2 = (int)magic_bits(v2);
        int zv3 = (int)magic_bits(v3);

        float Au0 = __shfl_sync(FULL, shA, zu0);
        float Bu0 = __shfl_sync(FULL, shB, zu0);
        float Au1 = __shfl_sync(FULL, shA, zu1);
        float Bu1 = __shfl_sync(FULL, shB, zu1);
        float Au2 = __shfl_sync(FULL, shA, zu2);
        float Bu2 = __shfl_sync(FULL, shB, zu2);
        float Au3 = __shfl_sync(FULL, shA, zu3);
        float Bu3 = __shfl_sync(FULL, shB, zu3);
        float Av0 = __shfl_sync(FULL, shA, zv0);
        float Bv0 = __shfl_sync(FULL, shB, zv0);
        float Av1 = __shfl_sync(FULL, shA, zv1);
        float Bv1 = __shfl_sync(FULL, shB, zv1);
        float Av2 = __shfl_sync(FULL, shA, zv2);
        float Bv2 = __shfl_sync(FULL, shB, zv2);
        float Av3 = __shfl_sync(FULL, shA, zv3);
        float Bv3 = __shfl_sync(FULL, shB, zv3);

        float e0 = fmaf(u0, Bu0, Au0);
        float e1 = fmaf(u1, Bu1, Au1);
        float e2 = fmaf(u2, Bu2, Au2);
        float e3 = fmaf(u3, Bu3, Au3);
        float f0 = fmaf(v0, Bv0, Av0);
        float f1 = fmaf(v1, Bv1, Av1);
        float f2 = fmaf(v2, Bv2, Av2);
        float f3 = fmaf(v3, Bv3, Av3);

        prod1 *= (e0 * e1) * (e2 * e3);
        prod2 *= (f0 * f1) * (f2 * f3);

        a0 = a1; b0 = b1; c0 = c1;
    }

    // att factor + sim writes
    {
        float attj = att_s[sj];
        float d1 = attj - att_s[sk1];
        float d2 = attj - att_s[sk2];
        float u1 = __fmaf_rn(16.0f, d1, -0.5f);   // u' = 16*diff - 0.5
        float u2 = __fmaf_rn(16.0f, d2, -0.5f);
        int z1 = (int)magic_bits(u1);
        int z2 = (int)magic_bits(u2);
        float A1 = __shfl_sync(FULL, shA, z1);
        float B1 = __shfl_sync(FULL, shB, z1);
        float A2 = __shfl_sync(FULL, shA, z2);
        float B2 = __shfl_sync(FULL, shB, z2);
        float sv1 = prod1 * fmaf(u1, B1, A1);
        float sv2 = prod2 * fmaf(u2, B2, A2);
        sim[sj  * M + sk1] = sv1;
        sim[sk1 * M + sj ] = sv1;
        sim[sj  * M + sk2] = sv2;
        sim[sk2 * M + sj ] = sv2;
    }
    __syncthreads();

    // ---- Phase 4: row sums (column-wise, conflict-free) -> rowinv ----
    {
        float s = 0.0f;
        #pragma unroll
        for (int it = 0; it < 4; it++)
            s += sim[(g + NG * it) * M + c];
        part[g * M + c] = s;
    }
    __syncthreads();
    if (tid < M) {
        float rs = 0.0f;
        #pragma unroll
        for (int gg = 0; gg < NG; gg++) rs += part[gg * M + tid];
        rowinv[tid] = 1.0f / rs;
    }
    __syncthreads();

    // ---- Phase 5: score accumulation (Am reused) ----
    float accA = 0.0f;
    #pragma unroll
    for (int it = 0; it < 4; it++) {
        const int r = g + NG * it;
        accA += Am[r * M + c] * rowinv[r];
    }
    accA *= rowinv[c];

    float corr = 0.0f;
    if (tid < M) {
        float a = att_s[tid];
        float aa = a * a;
        uint32_t zb = magic_bits(__fmaf_rn(aa, 16.0f, -0.5f));
        float4 v03 = *(const float4*)(smem + (zb * 256u + C403));
        corr = fmaf(aa, v03.y, v03.x) * rowinv[tid];
    }

    float ra  = accA + corr;
    float rbv = dconf * (1.0f / 4096.0f) + attconf * (1.0f / 64.0f);
    #pragma unroll
    for (int off = 16; off > 0; off >>= 1) {
        ra  += __shfl_down_sync(FULL, ra,  off);
        rbv += __shfl_down_sync(FULL, rbv, off);
    }
    if (lane == 0) { wredA[wid] = ra; wredB[wid] = rbv; }
    __syncthreads();

    // ---- Phase 6: score -> one-hot * conf ----
    if (tid == 0) {
        float S = 0.0f, B = 0.0f;
        #pragma unroll
        for (int i = 0; i < NW; i++) { S += wredA[i]; B += wredB[i]; }

        float score = sqrtf(S + 1e-20f);
        uint32_t zb = magic_bits(__fmaf_rn(B, 16.0f, -0.5f));
        int slot = (int)(zb - 0x4B3FFFFFu);
        slot = (slot < 0) ? 0 : ((slot > 18) ? 18 : slot);
        float2 v7 = *(const float2*)(smem + OFF_T7 + (uint32_t)slot * 8u);
        float conf = fmaf(B, v7.y, v7.x);

        float sc = fminf(fmaxf(score, 0.0f), (float)OBJ);
        int   i0 = (int)sc;
        float fr = sc - floorf(sc);
        int   i1 = (i0 + 1 <= OBJ) ? (i0 + 1) : OBJ;

        #pragma unroll
        for (int o = 0; o <= OBJ; o++) {
            float v = 0.0f;
            if (o == i0) v += (1.0f - fr);
            if (o == i1) v += fr;
            out[bi * (OBJ + 1) + o] = conf * v;
        }
    }
}

extern "C" void kernel_launch(void* const* d_in, const int* in_sizes, int n_in,
                              void* d_out, int out_size) {
    const float* boxes = (const float*)d_in[0];   // (n,4,64)
    const float* attn  = (const float*)d_in[1];   // (n,64)
    const float* fwts  = (const float*)d_in[2];   // (16,17)
    float* out = (float*)d_out;                   // (n,11)

    cudaFuncSetAttribute(counter_kernel,
                         cudaFuncAttributeMaxDynamicSharedMemorySize, SMEM_TOTAL);

    const int n = in_sizes[1] / M;                // 128
    counter_kernel<<<n, NT, SMEM_TOTAL>>>(boxes, attn, fwts, out);
}